// round 16
// baseline (speedup 1.0000x reference)
#include <cuda_runtime.h>
#include <cuda_fp16.h>
#include <cstdint>

#define TT 16384
#define DD 1024
#define II 2048
#define NE 16
#define NG 17              // 16 routed experts + shared expert as group 16
#define BM 128
#define RMAX (2 * TT + NG * BM)   // 34944 padded grouped rows max
#define MAXT (RMAX / BM)          // 273 row tiles max

#define BK 64
#define LDS_ 72            // halves per smem row (144 B, 16B-aligned, LDSM conflict-free)
#define ROWB (LDS_ * 2)    // 144 bytes per row
#define ASZ (BM * ROWB)    // 18432 B  (128 x 64 halves padded)
#define BSZ64 (64 * ROWB)  //  9216 B
#define BSZ128 (128 * ROWB)// 18432 B
#define STG1 (ASZ + 2 * BSZ64)   // 36864 per stage (A + B1 + B3)
#define STG2 (ASZ + BSZ128)      // 36864 per stage (A + B)

#define RBLK 512           // router blocks (32 tokens each, 8 warps x 4)
#define RSMEM (NE * DD * 4)  // 64 KB: full router weight matrix in smem

// ---------------- device scratch (static: no allocations allowed) -----------
__device__ int   d_expert[TT];
__device__ float d_wgt[TT];
__device__ int   d_cnt[NG];
__device__ int   d_off[NG + 1];
__device__ int   d_fill[NG];
__device__ int   d_inv[RMAX];                   // routed row -> token
__device__ int   d_tileG[MAXT];
__device__ int   d_tileR[MAXT];
__device__ int   d_ntiles;
__device__ int   d_done;                        // router completion ticket
__device__ __half d_xg[(size_t)RMAX * DD];      // grouped, scaled inputs (fp16)
__device__ __half d_hbuf[(size_t)RMAX * II];    // SwiGLU intermediate (fp16)
__device__ __half d_w1h[(size_t)NG * II * DD];  // fp16 weights, slot 16 = shared
__device__ __half d_w3h[(size_t)NG * II * DD];
__device__ __half d_w2h[(size_t)NG * DD * II];

// ---------------- helpers ---------------------------------------------------
__device__ __forceinline__ uint32_t smem_u32(const void* p) {
    uint32_t a;
    asm("{ .reg .u64 t; cvta.to.shared.u64 t, %1; cvt.u32.u64 %0, t; }"
        : "=r"(a) : "l"(p));
    return a;
}
__device__ __forceinline__ float silu_f(float v) { return v / (1.f + __expf(-v)); }

#define MMA_16816(C, A, B)                                                     \
    asm volatile(                                                              \
        "mma.sync.aligned.m16n8k16.row.col.f32.f16.f16.f32 "                   \
        "{%0,%1,%2,%3}, {%4,%5,%6,%7}, {%8,%9}, {%0,%1,%2,%3};\n"              \
        : "+f"((C)[0]), "+f"((C)[1]), "+f"((C)[2]), "+f"((C)[3])               \
        : "r"((A)[0]), "r"((A)[1]), "r"((A)[2]), "r"((A)[3]),                  \
          "r"((B)[0]), "r"((B)[1]))

#define LDSM4(R0, R1, R2, R3, ADDR)                                            \
    asm volatile("ldmatrix.sync.aligned.m8n8.x4.shared.b16 {%0,%1,%2,%3}, [%4];" \
        : "=r"(R0), "=r"(R1), "=r"(R2), "=r"(R3) : "r"(ADDR))

#define CP16(dst, src) \
    asm volatile("cp.async.cg.shared.global [%0], [%1], 16;" :: "r"(dst), "l"(src))
#define CPCOMMIT() asm volatile("cp.async.commit_group;" ::: "memory")
#define CPWAIT0()  asm volatile("cp.async.wait_group 0;" ::: "memory")
#define REDADD2(ptr, v0, v1)                                                   \
    asm volatile("red.global.add.v2.f32 [%0], {%1, %2};"                       \
                 :: "l"(ptr), "f"(v0), "f"(v1) : "memory")

// ---------------- kernel 0: zero counters ------------------------------------
__global__ void k_zero() {
    int i = threadIdx.x;
    if (i < NG) d_cnt[i] = 0;
    if (i == NG) d_done = 0;
}

// ---------------- weight fp32->fp16 convert (one expert set + shared) --------
__global__ void k_conv(const float4* __restrict__ se, const float4* __restrict__ ss,
                       __half2* __restrict__ d) {
    const int n4e = NE * II * DD / 4;
    const int n4s = II * DD / 4;
    const int n4 = n4e + n4s;
    int stride = gridDim.x * blockDim.x;
    for (int i = blockIdx.x * blockDim.x + threadIdx.x; i < n4; i += stride) {
        float4 v = (i < n4e) ? se[i] : ss[i - n4e];
        d[2 * i]     = __floats2half2_rn(v.x, v.y);
        d[2 * i + 1] = __floats2half2_rn(v.z, v.w);
    }
}

// ---------------- router: wr staged in smem, 32 tokens/block -----------------
__global__ void __launch_bounds__(256) k_router_off(const float* __restrict__ x,
                                                    const float* __restrict__ wr) {
    extern __shared__ __align__(16) float swr[];   // [NE * DD] = 64 KB
    int tid = threadIdx.x;
    // stage the full router matrix into smem (float4, coalesced)
    {
        float4* dst = (float4*)swr;
        const float4* src = (const float4*)wr;
#pragma unroll
        for (int i = 0; i < NE * DD / 4 / 256; i++)
            dst[tid + i * 256] = src[tid + i * 256];
    }
    __syncthreads();

    int warp = tid >> 5, lane = tid & 31;
#pragma unroll 1
    for (int it = 0; it < 4; it++) {
        int t = blockIdx.x * 32 + it * 8 + warp;
        const float4* xr = (const float4*)(x + (size_t)t * DD);
        float acc[NE];
#pragma unroll
        for (int e = 0; e < NE; e++) acc[e] = 0.f;
#pragma unroll
        for (int j = 0; j < DD / 4 / 32; j++) {
            int idx = lane + j * 32;
            float4 xv = xr[idx];
#pragma unroll
            for (int e = 0; e < NE; e++) {
                float4 wv = ((const float4*)(swr + e * DD))[idx];
                acc[e] = fmaf(xv.x, wv.x,
                         fmaf(xv.y, wv.y,
                         fmaf(xv.z, wv.z,
                         fmaf(xv.w, wv.w, acc[e]))));
            }
        }
        float best = -1e30f;
        int be = 0;
#pragma unroll
        for (int e = 0; e < NE; e++) {
            double v = (double)acc[e];
#pragma unroll
            for (int o = 16; o; o >>= 1) v += __shfl_xor_sync(0xffffffffu, v, o);
            float fv = (float)v;
            if (fv > best) { best = fv; be = e; }
        }
        if (lane == 0) {
            d_expert[t] = be;
            d_wgt[t] = 1.f / (1.f + expf(-best));
            atomicAdd(&d_cnt[be], 1);
        }
    }
    // completion ticket: last block computes offsets + tile list
    __syncthreads();
    if (tid == 0) {
        __threadfence();
        int done = atomicAdd(&d_done, 1);
        if (done == RBLK - 1) {
            int acc2 = 0, nt = 0;
            for (int g = 0; g < NG; g++) {
                int c = (g == NG - 1) ? TT : d_cnt[g];
                int tiles = (c + BM - 1) / BM;
                d_off[g] = acc2;
                d_fill[g] = acc2;
                for (int i = 0; i < tiles; i++) {
                    d_tileG[nt] = g;
                    d_tileR[nt] = acc2 + i * BM;
                    nt++;
                }
                acc2 += tiles * BM;
            }
            d_off[NG] = acc2;
            d_ntiles = nt;
            d_done = 0;
            __threadfence();
        }
    }
}

// ---------------- scatter tokens + zero padding rows + zero out --------------
__global__ void k_scatterpad(const float* __restrict__ x, float* __restrict__ out) {
    int t = blockIdx.x;
    __shared__ int sp;
    __shared__ float sw;
    if (threadIdx.x == 0) {
        int e = d_expert[t];
        sp = atomicAdd(&d_fill[e], 1);
        sw = d_wgt[t];
        d_inv[sp] = t;
    }
    __syncthreads();
    int pos = sp;
    float w = sw;
    int base16 = d_off[NG - 1];
    const float4* src = (const float4*)(x + (size_t)t * DD);
    __half* dst0 = d_xg + (size_t)pos * DD;
    __half* dst1 = d_xg + (size_t)(base16 + t) * DD;
    float4* orow = (float4*)(out + (size_t)t * DD);
    const float4 z4 = make_float4(0.f, 0.f, 0.f, 0.f);
    for (int j = threadIdx.x; j < DD / 4; j += blockDim.x) {
        float4 v = src[j];
        *((__half2*)(dst0 + j * 4))     = __floats2half2_rn(v.x * w, v.y * w);
        *((__half2*)(dst0 + j * 4 + 2)) = __floats2half2_rn(v.z * w, v.w * w);
        *((__half2*)(dst1 + j * 4))     = __floats2half2_rn(v.x, v.y);
        *((__half2*)(dst1 + j * 4 + 2)) = __floats2half2_rn(v.z, v.w);
        orow[j] = z4;
    }
    if (t < NG * BM) {
        int g = t / BM;
        int j = t % BM;
        int c = (g == NG - 1) ? TT : d_cnt[g];
        int row = d_off[g] + c + j;
        if (row < d_off[g + 1]) {
            float4* p = (float4*)(d_xg + (size_t)row * DD);
            p[threadIdx.x] = z4;
        }
    }
}

// ---------------- GEMM1: 128x(64+64)x64 tiles, 2-stage pipeline, SwiGLU ------
__device__ __forceinline__ void fill1(uint32_t base, int tid, int k0, int row0,
                                      int nbase, const __half* W1, const __half* W3) {
#pragma unroll
    for (int q = 0; q < 4; q++) {
        int idx = tid + q * 256;
        int r = idx >> 3, c = idx & 7;
        CP16(base + r * ROWB + c * 16,
             (const void*)(d_xg + (size_t)(row0 + r) * DD + k0 + c * 8));
    }
#pragma unroll
    for (int q = 0; q < 2; q++) {
        int idx = tid + q * 256;
        int r = idx >> 3, c = idx & 7;
        CP16(base + ASZ + r * ROWB + c * 16,
             (const void*)(W1 + (size_t)(nbase + r) * DD + k0 + c * 8));
    }
#pragma unroll
    for (int q = 0; q < 2; q++) {
        int idx = tid + q * 256;
        int r = idx >> 3, c = idx & 7;
        CP16(base + ASZ + BSZ64 + r * ROWB + c * 16,
             (const void*)(W3 + (size_t)(nbase + r) * DD + k0 + c * 8));
    }
    CPCOMMIT();
}

__global__ void __launch_bounds__(256, 2) k_ffn1() {
    extern __shared__ __align__(16) char smem[];
    int ty = blockIdx.y;
    if (ty >= d_ntiles) return;                 // grid: x = n-block (fast), y = m-tile
    int g = d_tileG[ty], row0 = d_tileR[ty], nbase = blockIdx.x * 64;
    const __half* W1 = d_w1h + (size_t)g * II * DD;
    const __half* W3 = d_w3h + (size_t)g * II * DD;
    uint32_t sb = smem_u32(smem);

    int tid = threadIdx.x;
    int warp = tid >> 5, lane = tid & 31;
    int wm = warp >> 1, wn = warp & 1;
    int gq = lane >> 2, ti = lane & 3;

    uint32_t a_off = (uint32_t)(wm * 32 + (lane & 15)) * ROWB + ((lane & 16) ? 16 : 0);
    uint32_t b_off = (uint32_t)((lane & 7) + ((lane & 16) ? 8 : 0)) * ROWB +
                     ((lane & 8) ? 16 : 0);
    uint32_t b1_off = ASZ + (uint32_t)(wn * 32) * ROWB + b_off;
    uint32_t b3_off = ASZ + BSZ64 + (uint32_t)(wn * 32) * ROWB + b_off;

    float c1[2][4][4], c3[2][4][4];
#pragma unroll
    for (int a = 0; a < 2; a++)
#pragma unroll
        for (int b = 0; b < 4; b++)
#pragma unroll
            for (int c = 0; c < 4; c++) { c1[a][b][c] = 0.f; c3[a][b][c] = 0.f; }

    fill1(sb, tid, 0, row0, nbase, W1, W3);
    const int NC = DD / BK;  // 16
    for (int i = 0; i < NC; i++) {
        CPWAIT0();
        __syncthreads();
        if (i + 1 < NC)
            fill1(sb + ((i + 1) & 1) * STG1, tid, (i + 1) * BK, row0, nbase, W1, W3);
        uint32_t st = sb + (i & 1) * STG1;
#pragma unroll
        for (int kk = 0; kk < BK / 16; kk++) {
            uint32_t a[2][4], b1f[4][2], b3f[4][2];
#pragma unroll
            for (int mf = 0; mf < 2; mf++)
                LDSM4(a[mf][0], a[mf][1], a[mf][2], a[mf][3],
                      st + a_off + (uint32_t)(mf * 16) * ROWB + kk * 32);
#pragma unroll
            for (int p = 0; p < 2; p++) {
                LDSM4(b1f[2 * p][0], b1f[2 * p][1], b1f[2 * p + 1][0], b1f[2 * p + 1][1],
                      st + b1_off + (uint32_t)(p * 16) * ROWB + kk * 32);
                LDSM4(b3f[2 * p][0], b3f[2 * p][1], b3f[2 * p + 1][0], b3f[2 * p + 1][1],
                      st + b3_off + (uint32_t)(p * 16) * ROWB + kk * 32);
            }
#pragma unroll
            for (int mf = 0; mf < 2; mf++)
#pragma unroll
                for (int nf = 0; nf < 4; nf++) {
                    MMA_16816(c1[mf][nf], a[mf], b1f[nf]);
                    MMA_16816(c3[mf][nf], a[mf], b3f[nf]);
                }
        }
    }

#pragma unroll
    for (int mf = 0; mf < 2; mf++) {
        int r0 = row0 + wm * 32 + mf * 16 + gq;
#pragma unroll
        for (int nf = 0; nf < 4; nf++) {
            int col = nbase + wn * 32 + nf * 8 + 2 * ti;
            float v0 = silu_f(c1[mf][nf][0]) * c3[mf][nf][0];
            float v1 = silu_f(c1[mf][nf][1]) * c3[mf][nf][1];
            float v2 = silu_f(c1[mf][nf][2]) * c3[mf][nf][2];
            float v3 = silu_f(c1[mf][nf][3]) * c3[mf][nf][3];
            *(__half2*)(d_hbuf + (size_t)r0 * II + col)       = __floats2half2_rn(v0, v1);
            *(__half2*)(d_hbuf + (size_t)(r0 + 8) * II + col) = __floats2half2_rn(v2, v3);
        }
    }
}

// ---------------- GEMM2: 128x128x64 tiles, single launch, red.add.v2 ---------
__device__ __forceinline__ void fill2(uint32_t base, int tid, int k0, int row0,
                                      int nbase, const __half* W) {
#pragma unroll
    for (int q = 0; q < 4; q++) {
        int idx = tid + q * 256;
        int r = idx >> 3, c = idx & 7;
        CP16(base + r * ROWB + c * 16,
             (const void*)(d_hbuf + (size_t)(row0 + r) * II + k0 + c * 8));
    }
#pragma unroll
    for (int q = 0; q < 4; q++) {
        int idx = tid + q * 256;
        int r = idx >> 3, c = idx & 7;
        CP16(base + ASZ + r * ROWB + c * 16,
             (const void*)(W + (size_t)(nbase + r) * II + k0 + c * 8));
    }
    CPCOMMIT();
}

__global__ void __launch_bounds__(256, 2) k_ffn2(float* __restrict__ out) {
    extern __shared__ __align__(16) char smem[];
    int nt = d_ntiles;
    int ty = blockIdx.y;
    if (ty >= nt) return;
    int g = d_tileG[ty], row0 = d_tileR[ty], nbase = blockIdx.x * 128;
    const __half* W = d_w2h + (size_t)g * DD * II;
    uint32_t sb = smem_u32(smem);

    int tid = threadIdx.x;
    int warp = tid >> 5, lane = tid & 31;
    int wm = warp >> 1, wn = warp & 1;          // 4 x 2 warps; warp tile 32 x 64
    int gq = lane >> 2, ti = lane & 3;

    uint32_t a_off = (uint32_t)(wm * 32 + (lane & 15)) * ROWB + ((lane & 16) ? 16 : 0);
    uint32_t b_off = ASZ +
                     (uint32_t)(wn * 64 + (lane & 7) + ((lane & 16) ? 8 : 0)) * ROWB +
                     ((lane & 8) ? 16 : 0);

    float cc[2][8][4];
#pragma unroll
    for (int a = 0; a < 2; a++)
#pragma unroll
        for (int b = 0; b < 8; b++)
#pragma unroll
            for (int c = 0; c < 4; c++) cc[a][b][c] = 0.f;

    fill2(sb, tid, 0, row0, nbase, W);
    const int NC = II / BK;  // 32
    for (int i = 0; i < NC; i++) {
        CPWAIT0();
        __syncthreads();
        if (i + 1 < NC)
            fill2(sb + ((i + 1) & 1) * STG2, tid, (i + 1) * BK, row0, nbase, W);
        uint32_t st = sb + (i & 1) * STG2;
#pragma unroll
        for (int kk = 0; kk < BK / 16; kk++) {
            uint32_t a[2][4], bf[8][2];
#pragma unroll
            for (int mf = 0; mf < 2; mf++)
                LDSM4(a[mf][0], a[mf][1], a[mf][2], a[mf][3],
                      st + a_off + (uint32_t)(mf * 16) * ROWB + kk * 32);
#pragma unroll
            for (int p = 0; p < 4; p++)
                LDSM4(bf[2 * p][0], bf[2 * p][1], bf[2 * p + 1][0], bf[2 * p + 1][1],
                      st + b_off + (uint32_t)(p * 16) * ROWB + kk * 32);
#pragma unroll
            for (int mf = 0; mf < 2; mf++)
#pragma unroll
                for (int nf = 0; nf < 8; nf++)
                    MMA_16816(cc[mf][nf], a[mf], bf[nf]);
        }
    }

    int base16 = d_off[NG - 1];
    int vend = d_off[g] + ((g == NG - 1) ? TT : d_cnt[g]);
#pragma unroll
    for (int mf = 0; mf < 2; mf++) {
#pragma unroll
        for (int h = 0; h < 2; h++) {
            int r = row0 + wm * 32 + mf * 16 + gq + h * 8;
            if (r < vend) {
                int t = (g == NG - 1) ? (r - base16) : d_inv[r];
                float* orow = out + (size_t)t * DD;
#pragma unroll
                for (int nf = 0; nf < 8; nf++) {
                    int col = nbase + wn * 64 + nf * 8 + 2 * ti;
                    REDADD2(orow + col, cc[mf][nf][2 * h], cc[mf][nf][2 * h + 1]);
                }
            }
        }
    }
}

// ---------------- launcher ----------------------------------------------------
extern "C" void kernel_launch(void* const* d_in, const int* in_sizes, int n_in,
                              void* d_out, int out_size) {
    const float* x   = (const float*)d_in[0];
    const float* wr  = (const float*)d_in[1];
    const float* w1  = (const float*)d_in[2];
    const float* w3  = (const float*)d_in[3];
    const float* w2  = (const float*)d_in[4];
    const float* wsg = (const float*)d_in[5];
    const float* wsu = (const float*)d_in[6];
    const float* wsd = (const float*)d_in[7];
    float* out = (float*)d_out;

    static bool init = false;
    static cudaStream_t s1, s2;
    static cudaEvent_t eFork, eMid, e1, e2;
    static __half* w1h;
    static __half* w3h;
    static __half* w2h;
    if (!init) {
        init = true;
        cudaFuncSetAttribute(k_ffn1, cudaFuncAttributeMaxDynamicSharedMemorySize,
                             2 * STG1);
        cudaFuncSetAttribute(k_ffn2, cudaFuncAttributeMaxDynamicSharedMemorySize,
                             2 * STG2);
        cudaFuncSetAttribute(k_router_off, cudaFuncAttributeMaxDynamicSharedMemorySize,
                             RSMEM);
        cudaStreamCreateWithFlags(&s1, cudaStreamNonBlocking);
        cudaStreamCreateWithFlags(&s2, cudaStreamNonBlocking);
        cudaEventCreateWithFlags(&eFork, cudaEventDisableTiming);
        cudaEventCreateWithFlags(&eMid, cudaEventDisableTiming);
        cudaEventCreateWithFlags(&e1, cudaEventDisableTiming);
        cudaEventCreateWithFlags(&e2, cudaEventDisableTiming);
        cudaGetSymbolAddress((void**)&w1h, d_w1h);
        cudaGetSymbolAddress((void**)&w3h, d_w3h);
        cudaGetSymbolAddress((void**)&w2h, d_w2h);
    }

    // main stream: zero + fork
    k_zero<<<1, 32>>>();
    cudaEventRecord(eFork, 0);
    cudaStreamWaitEvent(s1, eFork, 0);

    // branch s1: convert w1 + w3 (needed by ffn1) — overlaps router/scatter
    k_conv<<<2048, 256, 0, s1>>>((const float4*)w1, (const float4*)wsg, (__half2*)w1h);
    k_conv<<<2048, 256, 0, s1>>>((const float4*)w3, (const float4*)wsu, (__half2*)w3h);
    cudaEventRecord(e1, s1);

    // main stream: router -> scatter (independent of weight converts)
    k_router_off<<<RBLK, 256, RSMEM>>>(x, wr);
    k_scatterpad<<<TT, 128>>>(x, out);

    // branch s2: convert w2 — deferred so it rides under ffn1's idle DRAM
    cudaEventRecord(eMid, 0);
    cudaStreamWaitEvent(s2, eMid, 0);
    k_conv<<<2048, 256, 0, s2>>>((const float4*)w2, (const float4*)wsd, (__half2*)w2h);
    cudaEventRecord(e2, s2);

    // join: ffn1 needs w1h/w3h, ffn2 additionally needs w2h
    cudaStreamWaitEvent(0, e1, 0);
    k_ffn1<<<dim3(II / 64, MAXT), 256, 2 * STG1>>>();
    cudaStreamWaitEvent(0, e2, 0);
    k_ffn2<<<dim3(DD / 128, MAXT), 256, 2 * STG2>>>(out);
}

// round 17
// speedup vs baseline: 1.0762x; 1.0762x over previous
#include <cuda_runtime.h>
#include <cuda_fp16.h>
#include <cstdint>

#define TT 16384
#define DD 1024
#define II 2048
#define NE 16
#define NG 17              // 16 routed experts + shared expert as group 16
#define BM 128
#define RMAX (2 * TT + NG * BM)   // 34944 padded grouped rows max
#define MAXT (RMAX / BM)          // 273 row tiles max

#define BK 64
#define LDS_ 72            // halves per smem row (144 B, 16B-aligned, LDSM conflict-free)
#define ROWB (LDS_ * 2)    // 144 bytes per row
#define ASZ (BM * ROWB)    // 18432 B  (128 x 64 halves padded)
#define BSZ64 (64 * ROWB)  //  9216 B
#define BSZ128 (128 * ROWB)// 18432 B
#define STG1 (ASZ + 2 * BSZ64)   // 36864 per stage (A + B1 + B3)
#define STG2 (ASZ + BSZ128)      // 36864 per stage (A + B)

#define ROUTB (TT / 4)     // router blocks (4 tokens each)

// ---------------- device scratch (static: no allocations allowed) -----------
__device__ int   d_expert[TT];
__device__ float d_wgt[TT];
__device__ int   d_cnt[NG];
__device__ int   d_off[NG + 1];
__device__ int   d_fill[NG];
__device__ int   d_inv[RMAX];                   // routed row -> token
__device__ int   d_tileG[MAXT];
__device__ int   d_tileR[MAXT];
__device__ int   d_ntiles;
__device__ int   d_done;                        // router completion ticket
__device__ __half d_xg[(size_t)RMAX * DD];      // grouped, scaled inputs (fp16)
__device__ __half d_hbuf[(size_t)RMAX * II];    // SwiGLU intermediate (fp16)
__device__ __half d_w1h[(size_t)NG * II * DD];  // fp16 weights, slot 16 = shared
__device__ __half d_w3h[(size_t)NG * II * DD];
__device__ __half d_w2h[(size_t)NG * DD * II];

// ---------------- helpers ---------------------------------------------------
__device__ __forceinline__ uint32_t smem_u32(const void* p) {
    uint32_t a;
    asm("{ .reg .u64 t; cvta.to.shared.u64 t, %1; cvt.u32.u64 %0, t; }"
        : "=r"(a) : "l"(p));
    return a;
}
__device__ __forceinline__ float silu_f(float v) { return v / (1.f + __expf(-v)); }

#define MMA_16816(C, A, B)                                                     \
    asm volatile(                                                              \
        "mma.sync.aligned.m16n8k16.row.col.f32.f16.f16.f32 "                   \
        "{%0,%1,%2,%3}, {%4,%5,%6,%7}, {%8,%9}, {%0,%1,%2,%3};\n"              \
        : "+f"((C)[0]), "+f"((C)[1]), "+f"((C)[2]), "+f"((C)[3])               \
        : "r"((A)[0]), "r"((A)[1]), "r"((A)[2]), "r"((A)[3]),                  \
          "r"((B)[0]), "r"((B)[1]))

#define LDSM4(R0, R1, R2, R3, ADDR)                                            \
    asm volatile("ldmatrix.sync.aligned.m8n8.x4.shared.b16 {%0,%1,%2,%3}, [%4];" \
        : "=r"(R0), "=r"(R1), "=r"(R2), "=r"(R3) : "r"(ADDR))

#define CP16(dst, src) \
    asm volatile("cp.async.cg.shared.global [%0], [%1], 16;" :: "r"(dst), "l"(src))
#define CPCOMMIT() asm volatile("cp.async.commit_group;" ::: "memory")
#define CPWAIT0()  asm volatile("cp.async.wait_group 0;" ::: "memory")
#define REDADD2(ptr, v0, v1)                                                   \
    asm volatile("red.global.add.v2.f32 [%0], {%1, %2};"                       \
                 :: "l"(ptr), "f"(v0), "f"(v1) : "memory")

// ---------------- kernel 0: zero counters ------------------------------------
__global__ void k_zero() {
    int i = threadIdx.x;
    if (i < NG) d_cnt[i] = 0;
    if (i == NG) d_done = 0;
}

// ---------------- weight fp32->fp16 convert (one expert set + shared) --------
__global__ void k_conv(const float4* __restrict__ se, const float4* __restrict__ ss,
                       __half2* __restrict__ d) {
    const int n4e = NE * II * DD / 4;
    const int n4s = II * DD / 4;
    const int n4 = n4e + n4s;
    int stride = gridDim.x * blockDim.x;
    for (int i = blockIdx.x * blockDim.x + threadIdx.x; i < n4; i += stride) {
        float4 v = (i < n4e) ? se[i] : ss[i - n4e];
        d[2 * i]     = __floats2half2_rn(v.x, v.y);
        d[2 * i + 1] = __floats2half2_rn(v.z, v.w);
    }
}

// ---------------- router (float4 loads, fp32 reduce) + offsets/tile list -----
__global__ void k_router_off(const float* __restrict__ x, const float* __restrict__ wr) {
    int warp = threadIdx.x >> 5, lane = threadIdx.x & 31;
    int t = blockIdx.x * 4 + warp;
    const float4* xr = (const float4*)(x + (size_t)t * DD);
    float acc[NE];
#pragma unroll
    for (int e = 0; e < NE; e++) acc[e] = 0.f;
#pragma unroll
    for (int j = 0; j < DD / 4 / 32; j++) {
        int idx = lane + j * 32;
        float4 xv = xr[idx];
#pragma unroll
        for (int e = 0; e < NE; e++) {
            float4 wv = ((const float4*)(wr + e * DD))[idx];
            acc[e] = fmaf(xv.x, wv.x,
                     fmaf(xv.y, wv.y,
                     fmaf(xv.z, wv.z,
                     fmaf(xv.w, wv.w, acc[e]))));
        }
    }
    // cross-lane reduce all 16 accumulators in fp32 (butterfly), then argmax
#pragma unroll
    for (int o = 16; o; o >>= 1) {
#pragma unroll
        for (int e = 0; e < NE; e++)
            acc[e] += __shfl_xor_sync(0xffffffffu, acc[e], o);
    }
    float best = -1e30f;
    int be = 0;
#pragma unroll
    for (int e = 0; e < NE; e++) {
        if (acc[e] > best) { best = acc[e]; be = e; }   // strict >: first index wins
    }
    if (lane == 0) {
        d_expert[t] = be;
        d_wgt[t] = 1.f / (1.f + expf(-best));
        atomicAdd(&d_cnt[be], 1);
    }
    __syncthreads();
    if (threadIdx.x == 0) {
        __threadfence();
        int done = atomicAdd(&d_done, 1);
        if (done == ROUTB - 1) {
            int acc2 = 0, nt = 0;
            for (int g = 0; g < NG; g++) {
                int c = (g == NG - 1) ? TT : d_cnt[g];
                int tiles = (c + BM - 1) / BM;
                d_off[g] = acc2;
                d_fill[g] = acc2;
                for (int i = 0; i < tiles; i++) {
                    d_tileG[nt] = g;
                    d_tileR[nt] = acc2 + i * BM;
                    nt++;
                }
                acc2 += tiles * BM;
            }
            d_off[NG] = acc2;
            d_ntiles = nt;
            d_done = 0;
            __threadfence();
        }
    }
}

// ---------------- scatter tokens + zero padding rows + zero out --------------
__global__ void k_scatterpad(const float* __restrict__ x, float* __restrict__ out) {
    int t = blockIdx.x;
    __shared__ int sp;
    __shared__ float sw;
    if (threadIdx.x == 0) {
        int e = d_expert[t];
        sp = atomicAdd(&d_fill[e], 1);
        sw = d_wgt[t];
        d_inv[sp] = t;
    }
    __syncthreads();
    int pos = sp;
    float w = sw;
    int base16 = d_off[NG - 1];
    const float4* src = (const float4*)(x + (size_t)t * DD);
    __half* dst0 = d_xg + (size_t)pos * DD;
    __half* dst1 = d_xg + (size_t)(base16 + t) * DD;
    float4* orow = (float4*)(out + (size_t)t * DD);
    const float4 z4 = make_float4(0.f, 0.f, 0.f, 0.f);
    for (int j = threadIdx.x; j < DD / 4; j += blockDim.x) {
        float4 v = src[j];
        *((__half2*)(dst0 + j * 4))     = __floats2half2_rn(v.x * w, v.y * w);
        *((__half2*)(dst0 + j * 4 + 2)) = __floats2half2_rn(v.z * w, v.w * w);
        *((__half2*)(dst1 + j * 4))     = __floats2half2_rn(v.x, v.y);
        *((__half2*)(dst1 + j * 4 + 2)) = __floats2half2_rn(v.z, v.w);
        orow[j] = z4;
    }
    if (t < NG * BM) {
        int g = t / BM;
        int j = t % BM;
        int c = (g == NG - 1) ? TT : d_cnt[g];
        int row = d_off[g] + c + j;
        if (row < d_off[g + 1]) {
            float4* p = (float4*)(d_xg + (size_t)row * DD);
            p[threadIdx.x] = z4;
        }
    }
}

// ---------------- GEMM1: 128x(64+64)x64 tiles, 2-stage pipeline, SwiGLU ------
__device__ __forceinline__ void fill1(uint32_t base, int tid, int k0, int row0,
                                      int nbase, const __half* W1, const __half* W3) {
#pragma unroll
    for (int q = 0; q < 4; q++) {
        int idx = tid + q * 256;
        int r = idx >> 3, c = idx & 7;
        CP16(base + r * ROWB + c * 16,
             (const void*)(d_xg + (size_t)(row0 + r) * DD + k0 + c * 8));
    }
#pragma unroll
    for (int q = 0; q < 2; q++) {
        int idx = tid + q * 256;
        int r = idx >> 3, c = idx & 7;
        CP16(base + ASZ + r * ROWB + c * 16,
             (const void*)(W1 + (size_t)(nbase + r) * DD + k0 + c * 8));
    }
#pragma unroll
    for (int q = 0; q < 2; q++) {
        int idx = tid + q * 256;
        int r = idx >> 3, c = idx & 7;
        CP16(base + ASZ + BSZ64 + r * ROWB + c * 16,
             (const void*)(W3 + (size_t)(nbase + r) * DD + k0 + c * 8));
    }
    CPCOMMIT();
}

__global__ void __launch_bounds__(256, 2) k_ffn1() {
    extern __shared__ __align__(16) char smem[];
    int ty = blockIdx.y;
    if (ty >= d_ntiles) return;                 // grid: x = n-block (fast), y = m-tile
    int g = d_tileG[ty], row0 = d_tileR[ty], nbase = blockIdx.x * 64;
    const __half* W1 = d_w1h + (size_t)g * II * DD;
    const __half* W3 = d_w3h + (size_t)g * II * DD;
    uint32_t sb = smem_u32(smem);

    int tid = threadIdx.x;
    int warp = tid >> 5, lane = tid & 31;
    int wm = warp >> 1, wn = warp & 1;
    int gq = lane >> 2, ti = lane & 3;

    uint32_t a_off = (uint32_t)(wm * 32 + (lane & 15)) * ROWB + ((lane & 16) ? 16 : 0);
    uint32_t b_off = (uint32_t)((lane & 7) + ((lane & 16) ? 8 : 0)) * ROWB +
                     ((lane & 8) ? 16 : 0);
    uint32_t b1_off = ASZ + (uint32_t)(wn * 32) * ROWB + b_off;
    uint32_t b3_off = ASZ + BSZ64 + (uint32_t)(wn * 32) * ROWB + b_off;

    float c1[2][4][4], c3[2][4][4];
#pragma unroll
    for (int a = 0; a < 2; a++)
#pragma unroll
        for (int b = 0; b < 4; b++)
#pragma unroll
            for (int c = 0; c < 4; c++) { c1[a][b][c] = 0.f; c3[a][b][c] = 0.f; }

    fill1(sb, tid, 0, row0, nbase, W1, W3);
    const int NC = DD / BK;  // 16
    for (int i = 0; i < NC; i++) {
        CPWAIT0();
        __syncthreads();
        if (i + 1 < NC)
            fill1(sb + ((i + 1) & 1) * STG1, tid, (i + 1) * BK, row0, nbase, W1, W3);
        uint32_t st = sb + (i & 1) * STG1;
#pragma unroll
        for (int kk = 0; kk < BK / 16; kk++) {
            uint32_t a[2][4], b1f[4][2], b3f[4][2];
#pragma unroll
            for (int mf = 0; mf < 2; mf++)
                LDSM4(a[mf][0], a[mf][1], a[mf][2], a[mf][3],
                      st + a_off + (uint32_t)(mf * 16) * ROWB + kk * 32);
#pragma unroll
            for (int p = 0; p < 2; p++) {
                LDSM4(b1f[2 * p][0], b1f[2 * p][1], b1f[2 * p + 1][0], b1f[2 * p + 1][1],
                      st + b1_off + (uint32_t)(p * 16) * ROWB + kk * 32);
                LDSM4(b3f[2 * p][0], b3f[2 * p][1], b3f[2 * p + 1][0], b3f[2 * p + 1][1],
                      st + b3_off + (uint32_t)(p * 16) * ROWB + kk * 32);
            }
#pragma unroll
            for (int mf = 0; mf < 2; mf++)
#pragma unroll
                for (int nf = 0; nf < 4; nf++) {
                    MMA_16816(c1[mf][nf], a[mf], b1f[nf]);
                    MMA_16816(c3[mf][nf], a[mf], b3f[nf]);
                }
        }
    }

#pragma unroll
    for (int mf = 0; mf < 2; mf++) {
        int r0 = row0 + wm * 32 + mf * 16 + gq;
#pragma unroll
        for (int nf = 0; nf < 4; nf++) {
            int col = nbase + wn * 32 + nf * 8 + 2 * ti;
            float v0 = silu_f(c1[mf][nf][0]) * c3[mf][nf][0];
            float v1 = silu_f(c1[mf][nf][1]) * c3[mf][nf][1];
            float v2 = silu_f(c1[mf][nf][2]) * c3[mf][nf][2];
            float v3 = silu_f(c1[mf][nf][3]) * c3[mf][nf][3];
            *(__half2*)(d_hbuf + (size_t)r0 * II + col)       = __floats2half2_rn(v0, v1);
            *(__half2*)(d_hbuf + (size_t)(r0 + 8) * II + col) = __floats2half2_rn(v2, v3);
        }
    }
}

// ---------------- GEMM2: 128x128x64 tiles, single launch, red.add.v2 ---------
__device__ __forceinline__ void fill2(uint32_t base, int tid, int k0, int row0,
                                      int nbase, const __half* W) {
#pragma unroll
    for (int q = 0; q < 4; q++) {
        int idx = tid + q * 256;
        int r = idx >> 3, c = idx & 7;
        CP16(base + r * ROWB + c * 16,
             (const void*)(d_hbuf + (size_t)(row0 + r) * II + k0 + c * 8));
    }
#pragma unroll
    for (int q = 0; q < 4; q++) {
        int idx = tid + q * 256;
        int r = idx >> 3, c = idx & 7;
        CP16(base + ASZ + r * ROWB + c * 16,
             (const void*)(W + (size_t)(nbase + r) * II + k0 + c * 8));
    }
    CPCOMMIT();
}

__global__ void __launch_bounds__(256, 2) k_ffn2(float* __restrict__ out) {
    extern __shared__ __align__(16) char smem[];
    int nt = d_ntiles;
    int ty = blockIdx.y;
    if (ty >= nt) return;
    int g = d_tileG[ty], row0 = d_tileR[ty], nbase = blockIdx.x * 128;
    const __half* W = d_w2h + (size_t)g * DD * II;
    uint32_t sb = smem_u32(smem);

    int tid = threadIdx.x;
    int warp = tid >> 5, lane = tid & 31;
    int wm = warp >> 1, wn = warp & 1;          // 4 x 2 warps; warp tile 32 x 64
    int gq = lane >> 2, ti = lane & 3;

    uint32_t a_off = (uint32_t)(wm * 32 + (lane & 15)) * ROWB + ((lane & 16) ? 16 : 0);
    uint32_t b_off = ASZ +
                     (uint32_t)(wn * 64 + (lane & 7) + ((lane & 16) ? 8 : 0)) * ROWB +
                     ((lane & 8) ? 16 : 0);

    float cc[2][8][4];
#pragma unroll
    for (int a = 0; a < 2; a++)
#pragma unroll
        for (int b = 0; b < 8; b++)
#pragma unroll
            for (int c = 0; c < 4; c++) cc[a][b][c] = 0.f;

    fill2(sb, tid, 0, row0, nbase, W);
    const int NC = II / BK;  // 32
    for (int i = 0; i < NC; i++) {
        CPWAIT0();
        __syncthreads();
        if (i + 1 < NC)
            fill2(sb + ((i + 1) & 1) * STG2, tid, (i + 1) * BK, row0, nbase, W);
        uint32_t st = sb + (i & 1) * STG2;
#pragma unroll
        for (int kk = 0; kk < BK / 16; kk++) {
            uint32_t a[2][4], bf[8][2];
#pragma unroll
            for (int mf = 0; mf < 2; mf++)
                LDSM4(a[mf][0], a[mf][1], a[mf][2], a[mf][3],
                      st + a_off + (uint32_t)(mf * 16) * ROWB + kk * 32);
#pragma unroll
            for (int p = 0; p < 4; p++)
                LDSM4(bf[2 * p][0], bf[2 * p][1], bf[2 * p + 1][0], bf[2 * p + 1][1],
                      st + b_off + (uint32_t)(p * 16) * ROWB + kk * 32);
#pragma unroll
            for (int mf = 0; mf < 2; mf++)
#pragma unroll
                for (int nf = 0; nf < 8; nf++)
                    MMA_16816(cc[mf][nf], a[mf], bf[nf]);
        }
    }

    int base16 = d_off[NG - 1];
    int vend = d_off[g] + ((g == NG - 1) ? TT : d_cnt[g]);
#pragma unroll
    for (int mf = 0; mf < 2; mf++) {
#pragma unroll
        for (int h = 0; h < 2; h++) {
            int r = row0 + wm * 32 + mf * 16 + gq + h * 8;
            if (r < vend) {
                int t = (g == NG - 1) ? (r - base16) : d_inv[r];
                float* orow = out + (size_t)t * DD;
#pragma unroll
                for (int nf = 0; nf < 8; nf++) {
                    int col = nbase + wn * 64 + nf * 8 + 2 * ti;
                    REDADD2(orow + col, cc[mf][nf][2 * h], cc[mf][nf][2 * h + 1]);
                }
            }
        }
    }
}

// ---------------- launcher ----------------------------------------------------
extern "C" void kernel_launch(void* const* d_in, const int* in_sizes, int n_in,
                              void* d_out, int out_size) {
    const float* x   = (const float*)d_in[0];
    const float* wr  = (const float*)d_in[1];
    const float* w1  = (const float*)d_in[2];
    const float* w3  = (const float*)d_in[3];
    const float* w2  = (const float*)d_in[4];
    const float* wsg = (const float*)d_in[5];
    const float* wsu = (const float*)d_in[6];
    const float* wsd = (const float*)d_in[7];
    float* out = (float*)d_out;

    static bool init = false;
    static cudaStream_t s1, s2;
    static cudaEvent_t eFork, eMid, e1, e2;
    static __half* w1h;
    static __half* w3h;
    static __half* w2h;
    if (!init) {
        init = true;
        cudaFuncSetAttribute(k_ffn1, cudaFuncAttributeMaxDynamicSharedMemorySize,
                             2 * STG1);
        cudaFuncSetAttribute(k_ffn2, cudaFuncAttributeMaxDynamicSharedMemorySize,
                             2 * STG2);
        cudaStreamCreateWithFlags(&s1, cudaStreamNonBlocking);
        cudaStreamCreateWithFlags(&s2, cudaStreamNonBlocking);
        cudaEventCreateWithFlags(&eFork, cudaEventDisableTiming);
        cudaEventCreateWithFlags(&eMid, cudaEventDisableTiming);
        cudaEventCreateWithFlags(&e1, cudaEventDisableTiming);
        cudaEventCreateWithFlags(&e2, cudaEventDisableTiming);
        cudaGetSymbolAddress((void**)&w1h, d_w1h);
        cudaGetSymbolAddress((void**)&w3h, d_w3h);
        cudaGetSymbolAddress((void**)&w2h, d_w2h);
    }

    // main stream: zero + fork
    k_zero<<<1, 32>>>();
    cudaEventRecord(eFork, 0);
    cudaStreamWaitEvent(s1, eFork, 0);

    // branch s1: convert w1 + w3 (needed by ffn1) — overlaps router/scatter
    k_conv<<<2048, 256, 0, s1>>>((const float4*)w1, (const float4*)wsg, (__half2*)w1h);
    k_conv<<<2048, 256, 0, s1>>>((const float4*)w3, (const float4*)wsu, (__half2*)w3h);
    cudaEventRecord(e1, s1);

    // main stream: router -> scatter (independent of weight converts)
    k_router_off<<<ROUTB, 128>>>(x, wr);
    k_scatterpad<<<TT, 128>>>(x, out);

    // branch s2: convert w2 — deferred so it rides under ffn1's idle DRAM
    cudaEventRecord(eMid, 0);
    cudaStreamWaitEvent(s2, eMid, 0);
    k_conv<<<2048, 256, 0, s2>>>((const float4*)w2, (const float4*)wsd, (__half2*)w2h);
    cudaEventRecord(e2, s2);

    // join: ffn1 needs w1h/w3h, ffn2 additionally needs w2h
    cudaStreamWaitEvent(0, e1, 0);
    k_ffn1<<<dim3(II / 64, MAXT), 256, 2 * STG1>>>();
    cudaStreamWaitEvent(0, e2, 0);
    k_ffn2<<<dim3(DD / 128, MAXT), 256, 2 * STG2>>>(out);
}